// round 3
// baseline (speedup 1.0000x reference)
#include <cuda_runtime.h>

#define NS   2048
#define NI   384
#define NC   64
#define NH   8
#define NCH  8
#define HC   64
#define TS   128          // rows per tile
#define NT   (NS / TS)    // 16 tiles
#define TP   65           // smem tile row stride (floats) — conflict-free

// ---------------- scratch (device globals; no allocation) ----------------
__device__ float g_k[(size_t)NI * NS * 8];        // [i][s][ch]
__device__ float g_v[(size_t)NI * NS * 8];        // [i][s][ch]
__device__ float g_qpart[NT * NI * NC];           // [tile][i][c]
__device__ float g_q[NI * HC];                    // pre-scaled q
__device__ float g_ctx[NI * HC];                  // [i][h*8+ch]

// ---------------- packed fp32x2 helpers (FFMA2 path) ----------------
__device__ __forceinline__ unsigned long long pk2(float x, float y) {
    unsigned long long r;
    asm("mov.b64 %0, {%1, %2};" : "=l"(r) : "f"(x), "f"(y));
    return r;
}
__device__ __forceinline__ void upk2(unsigned long long v, float& x, float& y) {
    asm("mov.b64 {%0, %1}, %2;" : "=f"(x), "=f"(y) : "l"(v));
}
__device__ __forceinline__ unsigned long long f2fma(unsigned long long a,
                                                    unsigned long long b,
                                                    unsigned long long c) {
    unsigned long long d;
    asm("fma.rn.f32x2 %0, %1, %2, %3;" : "=l"(d) : "l"(a), "l"(b), "l"(c));
    return d;
}

// ==========================================================================
// Kernel 1: LN + k/v projection + per-block q_global partials.
// grid (NT, NI), block TS=128. One thread = one s-row.
// ==========================================================================
__global__ void __launch_bounds__(TS) k_pass1(
    const float* __restrict__ m, const float* __restrict__ mask,
    const float* __restrict__ gamma, const float* __restrict__ beta,
    const float* __restrict__ Wk, const float* __restrict__ Wv) {
    __shared__ float tile[TS * TP];
    __shared__ float sWT[NC * 16];   // [c][0..7]=Wk, [c][8..15]=Wv
    __shared__ float sg[NC], sb[NC];

    const int i  = blockIdx.y;
    const int s0 = blockIdx.x * TS;
    const int t  = threadIdx.x;

    for (int idx = t; idx < 8 * NC; idx += TS) {
        const int j = idx >> 6, c = idx & 63;
        sWT[c * 16 + j]     = Wk[idx];
        sWT[c * 16 + 8 + j] = Wv[idx];
    }
    if (t < NC) { sg[t] = gamma[t]; sb[t] = beta[t]; }
    for (int idx = t; idx < TS * NC; idx += TS) {
        const int r = idx >> 6, c = idx & 63;
        tile[r * TP + c] = m[((size_t)(s0 + r) * NI + i) * NC + c];
    }
    __syncthreads();

    float x[NC];
    float s1 = 0.f, s2 = 0.f;
#pragma unroll
    for (int c = 0; c < NC; c++) {
        const float v = tile[t * TP + c];
        x[c] = v; s1 += v; s2 += v * v;
    }
    const float mu   = s1 * (1.f / 64.f);
    const float var  = s2 * (1.f / 64.f) - mu * mu;
    const float rstd = rsqrtf(var + 1e-5f);
    const float maskv = mask[(size_t)(s0 + t) * NI + i];

    float ka[8], va[8];
#pragma unroll
    for (int j = 0; j < 8; j++) { ka[j] = 0.f; va[j] = 0.f; }

#pragma unroll
    for (int c = 0; c < NC; c++) {
        const float mn = (x[c] - mu) * rstd * sg[c] + sb[c];
        x[c] = mn;
        const float4 wk0 = *(const float4*)&sWT[c * 16];
        const float4 wk1 = *(const float4*)&sWT[c * 16 + 4];
        const float4 wv0 = *(const float4*)&sWT[c * 16 + 8];
        const float4 wv1 = *(const float4*)&sWT[c * 16 + 12];
        ka[0] += mn * wk0.x; ka[1] += mn * wk0.y; ka[2] += mn * wk0.z; ka[3] += mn * wk0.w;
        ka[4] += mn * wk1.x; ka[5] += mn * wk1.y; ka[6] += mn * wk1.z; ka[7] += mn * wk1.w;
        va[0] += mn * wv0.x; va[1] += mn * wv0.y; va[2] += mn * wv0.z; va[3] += mn * wv0.w;
        va[4] += mn * wv1.x; va[5] += mn * wv1.y; va[6] += mn * wv1.z; va[7] += mn * wv1.w;
    }

    float4* kp = (float4*)&g_k[((size_t)i * NS + s0 + t) * 8];
    float4* vp = (float4*)&g_v[((size_t)i * NS + s0 + t) * 8];
    kp[0] = make_float4(ka[0], ka[1], ka[2], ka[3]);
    kp[1] = make_float4(ka[4], ka[5], ka[6], ka[7]);
    vp[0] = make_float4(va[0], va[1], va[2], va[3]);
    vp[1] = make_float4(va[4], va[5], va[6], va[7]);

    // masked m_norm rows back into own tile row (safe: each thread owns row t)
#pragma unroll
    for (int c = 0; c < NC; c++) tile[t * TP + c] = x[c] * maskv;
    __syncthreads();

    if (t < NC) {
        float acc = 0.f;
        for (int r = 0; r < TS; r++) acc += tile[r * TP + t];
        g_qpart[((size_t)blockIdx.x * NI + i) * NC + t] = acc;
    }
}

// ==========================================================================
// Kernel 2: q = (sum_parts / clamp(denom)) @ Wq^T * 1/sqrt(8)
// grid NI, block 64.
// ==========================================================================
__global__ void __launch_bounds__(64) k_q(
    const float* __restrict__ mask, const float* __restrict__ Wq) {
    __shared__ float sqg[NC];
    __shared__ float sden[64];
    const int i = blockIdx.x;
    const int t = threadIdx.x;

    float acc = 0.f;
    for (int tt = 0; tt < NT; tt++)
        acc += g_qpart[((size_t)tt * NI + i) * NC + t];
    sqg[t] = acc;

    float d = 0.f;
    for (int s = t; s < NS; s += 64) d += mask[(size_t)s * NI + i];
    sden[t] = d;
    __syncthreads();
    for (int off = 32; off >= 1; off >>= 1) {
        if (t < off) sden[t] += sden[t + off];
        __syncthreads();
    }
    const float denom = fmaxf(sden[0], 1e-5f);

    float q = 0.f;
#pragma unroll
    for (int c = 0; c < NC; c++) q += sqg[c] * Wq[t * NC + c];
    g_q[i * HC + t] = q * 0.35355339059327373f / denom;   // * 1/sqrt(8) / denom
}

// ==========================================================================
// Kernel 3: attention per column. grid NI, block 256.
// ==========================================================================
__global__ void __launch_bounds__(256) k_attn(const float* __restrict__ mask) {
    __shared__ float sq[HC];
    __shared__ float wmax[8][NH];
    __shared__ float smaxf[NH];
    __shared__ float wsum[8][NH];
    __shared__ float wctx[8][HC];
    __shared__ float fsum[NH];

    const int i = blockIdx.x;
    const int t = threadIdx.x;
    const int w = t >> 5, lane = t & 31;

    if (t < HC) sq[t] = g_q[i * HC + t];
    __syncthreads();

    float lmax[NH];
#pragma unroll
    for (int h = 0; h < NH; h++) lmax[h] = -3.0e38f;

    for (int s = t; s < NS; s += 256) {
        const float4 ka = *(const float4*)&g_k[((size_t)i * NS + s) * 8];
        const float4 kb = *(const float4*)&g_k[((size_t)i * NS + s) * 8 + 4];
        const float mv = mask[(size_t)s * NI + i];
#pragma unroll
        for (int h = 0; h < NH; h++) {
            float l = sq[h*8+0]*ka.x + sq[h*8+1]*ka.y + sq[h*8+2]*ka.z + sq[h*8+3]*ka.w
                    + sq[h*8+4]*kb.x + sq[h*8+5]*kb.y + sq[h*8+6]*kb.z + sq[h*8+7]*kb.w;
            l = (mv > 0.f) ? l : -1e9f;
            lmax[h] = fmaxf(lmax[h], l);
        }
    }
#pragma unroll
    for (int h = 0; h < NH; h++) {
        float v = lmax[h];
        for (int d = 16; d; d >>= 1) v = fmaxf(v, __shfl_xor_sync(0xffffffffu, v, d));
        if (lane == 0) wmax[w][h] = v;
    }
    __syncthreads();
    if (t < NH) {
        float v = wmax[0][t];
        for (int ww = 1; ww < 8; ww++) v = fmaxf(v, wmax[ww][t]);
        smaxf[t] = v;
    }
    __syncthreads();
    float mx[NH];
#pragma unroll
    for (int h = 0; h < NH; h++) mx[h] = smaxf[h];

    float esum[NH];
    float cacc[HC];
#pragma unroll
    for (int h = 0; h < NH; h++) esum[h] = 0.f;
#pragma unroll
    for (int j = 0; j < HC; j++) cacc[j] = 0.f;

    for (int s = t; s < NS; s += 256) {
        const float4 ka = *(const float4*)&g_k[((size_t)i * NS + s) * 8];
        const float4 kb = *(const float4*)&g_k[((size_t)i * NS + s) * 8 + 4];
        const float4 va = *(const float4*)&g_v[((size_t)i * NS + s) * 8];
        const float4 vb = *(const float4*)&g_v[((size_t)i * NS + s) * 8 + 4];
        const float mv = mask[(size_t)s * NI + i];
#pragma unroll
        for (int h = 0; h < NH; h++) {
            float l = sq[h*8+0]*ka.x + sq[h*8+1]*ka.y + sq[h*8+2]*ka.z + sq[h*8+3]*ka.w
                    + sq[h*8+4]*kb.x + sq[h*8+5]*kb.y + sq[h*8+6]*kb.z + sq[h*8+7]*kb.w;
            l = (mv > 0.f) ? l : -1e9f;
            const float e = __expf(l - mx[h]);
            esum[h] += e;
            cacc[h*8+0] += e * va.x; cacc[h*8+1] += e * va.y;
            cacc[h*8+2] += e * va.z; cacc[h*8+3] += e * va.w;
            cacc[h*8+4] += e * vb.x; cacc[h*8+5] += e * vb.y;
            cacc[h*8+6] += e * vb.z; cacc[h*8+7] += e * vb.w;
        }
    }
#pragma unroll
    for (int h = 0; h < NH; h++) {
        float v = esum[h];
        for (int d = 16; d; d >>= 1) v += __shfl_xor_sync(0xffffffffu, v, d);
        if (lane == 0) wsum[w][h] = v;
    }
#pragma unroll
    for (int j = 0; j < HC; j++) {
        float v = cacc[j];
        for (int d = 16; d; d >>= 1) v += __shfl_xor_sync(0xffffffffu, v, d);
        if (lane == 0) wctx[w][j] = v;
    }
    __syncthreads();
    if (t < NH) {
        float v = 0.f;
        for (int ww = 0; ww < 8; ww++) v += wsum[ww][t];
        fsum[t] = v;
    }
    __syncthreads();
    if (t < HC) {
        float cs = 0.f;
        for (int ww = 0; ww < 8; ww++) cs += wctx[ww][t];
        g_ctx[i * HC + t] = cs / fsum[t >> 3];
    }
}

// ==========================================================================
// Kernel 4: LN + gate GEMM + sigmoid*ctx + out GEMM (FFMA2 path).
// grid (NT, NI), block TS=128. One thread = one s-row. Dynamic smem.
// ==========================================================================
__global__ void __launch_bounds__(TS) k_out(
    const float* __restrict__ m,
    const float* __restrict__ gamma, const float* __restrict__ beta,
    const float* __restrict__ Wg, const float* __restrict__ bg,
    const float* __restrict__ Wo, const float* __restrict__ bo,
    float* __restrict__ out) {
    extern __shared__ float dsm[];
    float* tile = dsm;                       // TS*TP = 8320 floats
    float* sWg  = dsm + TS * TP;             // 4096
    float* sWo  = sWg + 4096;                // 4096
    float* sbg  = sWo + 4096;                // 64
    float* sbo  = sbg + 64;                  // 64
    float* sctx = sbo + 64;                  // 64
    float* sgam = sctx + 64;                 // 64
    float* sbet = sgam + 64;                 // 64

    const int i  = blockIdx.y;
    const int s0 = blockIdx.x * TS;
    const int t  = threadIdx.x;

    for (int idx = t; idx < 4096; idx += TS) { sWg[idx] = Wg[idx]; sWo[idx] = Wo[idx]; }
    if (t < 64) {
        sbg[t] = bg[t]; sbo[t] = bo[t];
        sctx[t] = g_ctx[i * HC + t];
        sgam[t] = gamma[t]; sbet[t] = beta[t];
    }
    for (int idx = t; idx < TS * NC; idx += TS) {
        const int r = idx >> 6, c = idx & 63;
        tile[r * TP + c] = m[((size_t)(s0 + r) * NI + i) * NC + c];
    }
    __syncthreads();

    // LayerNorm in registers
    float x[NC];
    float s1 = 0.f, s2 = 0.f;
#pragma unroll
    for (int c = 0; c < NC; c++) {
        const float v = tile[t * TP + c];
        x[c] = v; s1 += v; s2 += v * v;
    }
    const float mu   = s1 * (1.f / 64.f);
    const float var  = s2 * (1.f / 64.f) - mu * mu;
    const float rstd = rsqrtf(var + 1e-5f);
#pragma unroll
    for (int c = 0; c < NC; c++) x[c] = (x[c] - mu) * rstd * sgam[c] + sbet[c];

    unsigned long long mn2[32];
#pragma unroll
    for (int cc = 0; cc < 32; cc++) mn2[cc] = pk2(x[2 * cc], x[2 * cc + 1]);

    // Gate GEMM: o[j] = ctx[j] * sigmoid(mn . Wg[j] + bg[j])
    float o[HC];
#pragma unroll
    for (int j = 0; j < HC; j++) {
        unsigned long long a0 = 0ull, a1 = 0ull;
#pragma unroll
        for (int q = 0; q < 16; q++) {
            const ulonglong2 wv = *(const ulonglong2*)&sWg[j * NC + 4 * q];
            a0 = f2fma(mn2[2 * q],     wv.x, a0);
            a1 = f2fma(mn2[2 * q + 1], wv.y, a1);
        }
        float p0, p1, p2, p3;
        upk2(a0, p0, p1); upk2(a1, p2, p3);
        const float gv = p0 + p1 + p2 + p3 + sbg[j];
        o[j] = sctx[j] * __fdividef(1.f, 1.f + __expf(-gv));
    }

    unsigned long long o2[32];
#pragma unroll
    for (int jj = 0; jj < 32; jj++) o2[jj] = pk2(o[2 * jj], o[2 * jj + 1]);

    // Out GEMM: out[c] = o . Wo[c] + bo[c]
#pragma unroll
    for (int c = 0; c < NC; c++) {
        unsigned long long a0 = 0ull, a1 = 0ull;
#pragma unroll
        for (int q = 0; q < 16; q++) {
            const ulonglong2 wv = *(const ulonglong2*)&sWo[c * NC + 4 * q];
            a0 = f2fma(o2[2 * q],     wv.x, a0);
            a1 = f2fma(o2[2 * q + 1], wv.y, a1);
        }
        float p0, p1, p2, p3;
        upk2(a0, p0, p1); upk2(a1, p2, p3);
        tile[t * TP + c] = p0 + p1 + p2 + p3 + sbo[c];
    }
    __syncthreads();

    for (int idx = t; idx < TS * NC; idx += TS) {
        const int r = idx >> 6, c = idx & 63;
        out[((size_t)(s0 + r) * NI + i) * NC + c] = tile[r * TP + c];
    }
}

// ==========================================================================
extern "C" void kernel_launch(void* const* d_in, const int* in_sizes, int n_in,
                              void* d_out, int out_size) {
    const float* m     = (const float*)d_in[0];
    const float* mask  = (const float*)d_in[1];
    const float* gamma = (const float*)d_in[2];
    const float* beta  = (const float*)d_in[3];
    const float* Wq    = (const float*)d_in[4];
    const float* Wk    = (const float*)d_in[5];
    const float* Wv    = (const float*)d_in[6];
    const float* Wg    = (const float*)d_in[7];
    const float* bg    = (const float*)d_in[8];
    const float* Wo    = (const float*)d_in[9];
    const float* bo    = (const float*)d_in[10];
    float* out = (float*)d_out;

    const int dsm_bytes = (TS * TP + 4096 + 4096 + 5 * 64) * 4;  // 67328 B
    cudaFuncSetAttribute(k_out, cudaFuncAttributeMaxDynamicSharedMemorySize, dsm_bytes);

    dim3 g1(NT, NI);
    k_pass1<<<g1, TS>>>(m, mask, gamma, beta, Wk, Wv);
    k_q<<<NI, 64>>>(mask, Wq);
    k_attn<<<NI, 256>>>(mask);
    dim3 g4(NT, NI);
    k_out<<<g4, TS, dsm_bytes>>>(m, gamma, beta, Wg, bg, Wo, bo, out);
}

// round 5
// speedup vs baseline: 1.9284x; 1.9284x over previous
#include <cuda_runtime.h>

#define NS   2048
#define NI   384
#define NC   64
#define NH   8
#define HC   64
#define TS   128          // rows per tile
#define NT   (NS / TS)    // 16 tiles
#define TP   65           // k_pass1 smem tile stride (scalar access only)
#define OTP  68           // k_out X/O tile stride (float4-aligned pad)
#define WTP  68           // k_out W^T stride

// ---------------- scratch (device globals; no allocation) ----------------
__device__ __align__(16) float g_k[(size_t)NI * NS * 8];   // [i][s][ch]
__device__ __align__(16) float g_v[(size_t)NI * NS * 8];   // [i][s][ch]
__device__ float g_qpart[NT * NI * NC];                    // [tile][i][c]
__device__ float g_q[NI * HC];                             // pre-scaled q
__device__ float g_ctx[NI * HC];                           // [i][h*8+ch]

// ---------------- packed fp32x2 helpers (FFMA2 path) ----------------
__device__ __forceinline__ unsigned long long pk2(float x, float y) {
    unsigned long long r;
    asm("mov.b64 %0, {%1, %2};" : "=l"(r) : "f"(x), "f"(y));
    return r;
}
__device__ __forceinline__ void upk2(unsigned long long v, float& x, float& y) {
    asm("mov.b64 {%0, %1}, %2;" : "=f"(x), "=f"(y) : "l"(v));
}
__device__ __forceinline__ unsigned long long f2fma(unsigned long long a,
                                                    unsigned long long b,
                                                    unsigned long long c) {
    unsigned long long d;
    asm("fma.rn.f32x2 %0, %1, %2, %3;" : "=l"(d) : "l"(a), "l"(b), "l"(c));
    return d;
}

// ==========================================================================
// Kernel 1: LN + k/v projection (FFMA2) + per-block q_global partials.
// grid (NT, NI), block TS=128. One thread = one s-row.
// ==========================================================================
__global__ void __launch_bounds__(TS) k_pass1(
    const float* __restrict__ m, const float* __restrict__ mask,
    const float* __restrict__ gamma, const float* __restrict__ beta,
    const float* __restrict__ Wk, const float* __restrict__ Wv) {
    __shared__ float tile[TS * TP];
    __shared__ __align__(16) float sWT[NC * 16];  // [c][0..7]=Wk, [c][8..15]=Wv
    __shared__ float sg[NC], sb[NC];

    const int i  = blockIdx.y;
    const int s0 = blockIdx.x * TS;
    const int t  = threadIdx.x;

    for (int idx = t; idx < 8 * NC; idx += TS) {
        const int j = idx >> 6, c = idx & 63;
        sWT[c * 16 + j]     = Wk[idx];
        sWT[c * 16 + 8 + j] = Wv[idx];
    }
    if (t < NC) { sg[t] = gamma[t]; sb[t] = beta[t]; }
    // float4 gmem load (16B aligned), scalar smem stores (TP=65 safe)
    for (int idx = t; idx < TS * NC / 4; idx += TS) {
        const int r = idx >> 4, c4 = (idx & 15) * 4;
        const float4 v = *(const float4*)&m[((size_t)(s0 + r) * NI + i) * NC + c4];
        tile[r * TP + c4 + 0] = v.x;
        tile[r * TP + c4 + 1] = v.y;
        tile[r * TP + c4 + 2] = v.z;
        tile[r * TP + c4 + 3] = v.w;
    }
    __syncthreads();

    float x[NC];
    float s1 = 0.f, s2 = 0.f;
#pragma unroll
    for (int c = 0; c < NC; c++) {
        const float v = tile[t * TP + c];
        x[c] = v; s1 += v; s2 += v * v;
    }
    const float mu   = s1 * (1.f / 64.f);
    const float var  = s2 * (1.f / 64.f) - mu * mu;
    const float rstd = rsqrtf(var + 1e-5f);
    const float maskv = mask[(size_t)(s0 + t) * NI + i];

    unsigned long long ka2[4], va2[4];
#pragma unroll
    for (int j = 0; j < 4; j++) { ka2[j] = 0ull; va2[j] = 0ull; }

#pragma unroll
    for (int c = 0; c < NC; c++) {
        const float mn = (x[c] - mu) * rstd * sg[c] + sb[c];
        x[c] = mn;
        const unsigned long long mp = pk2(mn, mn);
        const ulonglong2 wk  = *(const ulonglong2*)&sWT[c * 16];
        const ulonglong2 wk1 = *(const ulonglong2*)&sWT[c * 16 + 4];
        const ulonglong2 wv  = *(const ulonglong2*)&sWT[c * 16 + 8];
        const ulonglong2 wv1 = *(const ulonglong2*)&sWT[c * 16 + 12];
        ka2[0] = f2fma(mp, wk.x,  ka2[0]);
        ka2[1] = f2fma(mp, wk.y,  ka2[1]);
        ka2[2] = f2fma(mp, wk1.x, ka2[2]);
        ka2[3] = f2fma(mp, wk1.y, ka2[3]);
        va2[0] = f2fma(mp, wv.x,  va2[0]);
        va2[1] = f2fma(mp, wv.y,  va2[1]);
        va2[2] = f2fma(mp, wv1.x, va2[2]);
        va2[3] = f2fma(mp, wv1.y, va2[3]);
    }

    float kr[8], vr[8];
#pragma unroll
    for (int j = 0; j < 4; j++) {
        upk2(ka2[j], kr[2 * j], kr[2 * j + 1]);
        upk2(va2[j], vr[2 * j], vr[2 * j + 1]);
    }
    float4* kp = (float4*)&g_k[((size_t)i * NS + s0 + t) * 8];
    float4* vp = (float4*)&g_v[((size_t)i * NS + s0 + t) * 8];
    kp[0] = make_float4(kr[0], kr[1], kr[2], kr[3]);
    kp[1] = make_float4(kr[4], kr[5], kr[6], kr[7]);
    vp[0] = make_float4(vr[0], vr[1], vr[2], vr[3]);
    vp[1] = make_float4(vr[4], vr[5], vr[6], vr[7]);

#pragma unroll
    for (int c = 0; c < NC; c++) tile[t * TP + c] = x[c] * maskv;
    __syncthreads();

    if (t < NC) {
        float a0 = 0.f, a1 = 0.f, a2 = 0.f, a3 = 0.f;
        for (int r = 0; r < TS; r += 4) {
            a0 += tile[(r + 0) * TP + t];
            a1 += tile[(r + 1) * TP + t];
            a2 += tile[(r + 2) * TP + t];
            a3 += tile[(r + 3) * TP + t];
        }
        g_qpart[((size_t)blockIdx.x * NI + i) * NC + t] = (a0 + a1) + (a2 + a3);
    }
}

// ==========================================================================
// Kernel 2: q = (sum_parts / clamp(denom)) @ Wq^T * 1/sqrt(8). grid NI, blk 64.
// ==========================================================================
__global__ void __launch_bounds__(64) k_q(
    const float* __restrict__ mask, const float* __restrict__ Wq) {
    __shared__ float sqg[NC];
    __shared__ float sden[64];
    const int i = blockIdx.x;
    const int t = threadIdx.x;

    float acc = 0.f;
    for (int tt = 0; tt < NT; tt++)
        acc += g_qpart[((size_t)tt * NI + i) * NC + t];
    sqg[t] = acc;

    float d = 0.f;
    for (int s = t; s < NS; s += 64) d += mask[(size_t)s * NI + i];
    sden[t] = d;
    __syncthreads();
    for (int off = 32; off >= 1; off >>= 1) {
        if (t < off) sden[t] += sden[t + off];
        __syncthreads();
    }
    const float denom = fmaxf(sden[0], 1e-5f);

    float q = 0.f;
#pragma unroll
    for (int c = 0; c < NC; c++) q += sqg[c] * Wq[t * NC + c];
    g_q[i * HC + t] = q * 0.35355339059327373f / denom;
}

// ==========================================================================
// Kernel 3: attention per column. grid NI, block 256.
// ==========================================================================
__global__ void __launch_bounds__(256) k_attn(const float* __restrict__ mask) {
    __shared__ float sq[HC];
    __shared__ float wmax[8][NH];
    __shared__ float smaxf[NH];
    __shared__ float wsum[8][NH];
    __shared__ float wctx[8][HC];
    __shared__ float fsum[NH];

    const int i = blockIdx.x;
    const int t = threadIdx.x;
    const int w = t >> 5, lane = t & 31;

    if (t < HC) sq[t] = g_q[i * HC + t];
    __syncthreads();

    float lmax[NH];
#pragma unroll
    for (int h = 0; h < NH; h++) lmax[h] = -3.0e38f;

    for (int s = t; s < NS; s += 256) {
        const float4 ka = *(const float4*)&g_k[((size_t)i * NS + s) * 8];
        const float4 kb = *(const float4*)&g_k[((size_t)i * NS + s) * 8 + 4];
        const float mv = mask[(size_t)s * NI + i];
#pragma unroll
        for (int h = 0; h < NH; h++) {
            float l = sq[h*8+0]*ka.x + sq[h*8+1]*ka.y + sq[h*8+2]*ka.z + sq[h*8+3]*ka.w
                    + sq[h*8+4]*kb.x + sq[h*8+5]*kb.y + sq[h*8+6]*kb.z + sq[h*8+7]*kb.w;
            l = (mv > 0.f) ? l : -1e9f;
            lmax[h] = fmaxf(lmax[h], l);
        }
    }
#pragma unroll
    for (int h = 0; h < NH; h++) {
        float v = lmax[h];
        for (int d = 16; d; d >>= 1) v = fmaxf(v, __shfl_xor_sync(0xffffffffu, v, d));
        if (lane == 0) wmax[w][h] = v;
    }
    __syncthreads();
    if (t < NH) {
        float v = wmax[0][t];
        for (int ww = 1; ww < 8; ww++) v = fmaxf(v, wmax[ww][t]);
        smaxf[t] = v;
    }
    __syncthreads();
    float mx[NH];
#pragma unroll
    for (int h = 0; h < NH; h++) mx[h] = smaxf[h];

    float esum[NH];
    float cacc[HC];
#pragma unroll
    for (int h = 0; h < NH; h++) esum[h] = 0.f;
#pragma unroll
    for (int j = 0; j < HC; j++) cacc[j] = 0.f;

    for (int s = t; s < NS; s += 256) {
        const float4 ka = *(const float4*)&g_k[((size_t)i * NS + s) * 8];
        const float4 kb = *(const float4*)&g_k[((size_t)i * NS + s) * 8 + 4];
        const float4 va = *(const float4*)&g_v[((size_t)i * NS + s) * 8];
        const float4 vb = *(const float4*)&g_v[((size_t)i * NS + s) * 8 + 4];
        const float mv = mask[(size_t)s * NI + i];
#pragma unroll
        for (int h = 0; h < NH; h++) {
            float l = sq[h*8+0]*ka.x + sq[h*8+1]*ka.y + sq[h*8+2]*ka.z + sq[h*8+3]*ka.w
                    + sq[h*8+4]*kb.x + sq[h*8+5]*kb.y + sq[h*8+6]*kb.z + sq[h*8+7]*kb.w;
            l = (mv > 0.f) ? l : -1e9f;
            const float e = __expf(l - mx[h]);
            esum[h] += e;
            cacc[h*8+0] += e * va.x; cacc[h*8+1] += e * va.y;
            cacc[h*8+2] += e * va.z; cacc[h*8+3] += e * va.w;
            cacc[h*8+4] += e * vb.x; cacc[h*8+5] += e * vb.y;
            cacc[h*8+6] += e * vb.z; cacc[h*8+7] += e * vb.w;
        }
    }
#pragma unroll
    for (int h = 0; h < NH; h++) {
        float v = esum[h];
        for (int d = 16; d; d >>= 1) v += __shfl_xor_sync(0xffffffffu, v, d);
        if (lane == 0) wsum[w][h] = v;
    }
#pragma unroll
    for (int j = 0; j < HC; j++) {
        float v = cacc[j];
        for (int d = 16; d; d >>= 1) v += __shfl_xor_sync(0xffffffffu, v, d);
        if (lane == 0) wctx[w][j] = v;
    }
    __syncthreads();
    if (t < NH) {
        float v = 0.f;
        for (int ww = 0; ww < 8; ww++) v += wsum[ww][t];
        fsum[t] = v;
    }
    __syncthreads();
    if (t < HC) {
        float cs = 0.f;
        for (int ww = 0; ww < 8; ww++) cs += wctx[ww][t];
        g_ctx[i * HC + t] = cs / fsum[t >> 3];
    }
}

// ==========================================================================
// Kernel 4: LN + gate GEMM + sigmoid*ctx + out GEMM.
// Register-blocked 4x8 per thread, 256 threads, FFMA2, W^T in smem.
// grid (NT, NI). Dynamic smem.
// ==========================================================================
__global__ void __launch_bounds__(256) k_out(
    const float* __restrict__ m,
    const float* __restrict__ gamma, const float* __restrict__ beta,
    const float* __restrict__ Wg, const float* __restrict__ bg,
    const float* __restrict__ Wo, const float* __restrict__ bo,
    float* __restrict__ out) {
    extern __shared__ float dsm[];
    float* tile  = dsm;                       // TS*OTP = 8704 floats (X then O)
    float* sWgT  = tile + TS * OTP;           // 64*WTP = 4352
    float* sWoT  = sWgT + NC * WTP;           // 4352
    float* sbg   = sWoT + NC * WTP;           // 64
    float* sbo   = sbg + 64;                  // 64
    float* sctx  = sbo + 64;                  // 64
    float* sgam  = sctx + 64;                 // 64
    float* sbet  = sgam + 64;                 // 64

    const int i  = blockIdx.y;
    const int s0 = blockIdx.x * TS;
    const int t  = threadIdx.x;

    // load + transpose weights: sW?T[c][j] = W?[j][c]
    for (int idx = t; idx < NC * NC; idx += 256) {
        const int j = idx >> 6, c = idx & 63;
        sWgT[c * WTP + j] = Wg[idx];
        sWoT[c * WTP + j] = Wo[idx];
    }
    if (t < 64) {
        sbg[t] = bg[t]; sbo[t] = bo[t];
        sctx[t] = g_ctx[i * HC + t];
        sgam[t] = gamma[t]; sbet[t] = beta[t];
    }
    // load X tile (float4 both sides; OTP=68 keeps 16B alignment)
    for (int idx = t; idx < TS * NC / 4; idx += 256) {
        const int r = idx >> 4, c4 = (idx & 15) * 4;
        *(float4*)&tile[r * OTP + c4] =
            *(const float4*)&m[((size_t)(s0 + r) * NI + i) * NC + c4];
    }
    __syncthreads();

    // LayerNorm: 2 threads per row (t>>1 = row, t&1 = half)
    {
        const int r = t >> 1;
        const int h = (t & 1) * 32;
        float xv[32];
        float s1 = 0.f, s2 = 0.f;
#pragma unroll
        for (int c = 0; c < 32; c++) {
            const float v = tile[r * OTP + h + c];
            xv[c] = v; s1 += v; s2 += v * v;
        }
        s1 += __shfl_xor_sync(0xffffffffu, s1, 1);
        s2 += __shfl_xor_sync(0xffffffffu, s2, 1);
        const float mu   = s1 * (1.f / 64.f);
        const float var  = s2 * (1.f / 64.f) - mu * mu;
        const float rstd = rsqrtf(var + 1e-5f);
#pragma unroll
        for (int c = 0; c < 32; c++)
            tile[r * OTP + h + c] = (xv[c] - mu) * rstd * sgam[h + c] + sbet[h + c];
    }
    __syncthreads();

    const int cg = t & 7;          // col group: cols cg*8 .. cg*8+7
    const int rg = t >> 3;         // row group: rows rg, rg+32, rg+64, rg+96
    const int n0 = cg * 8;

    unsigned long long acc[4][4];

    // ---------------- GEMM1: G = X @ Wg^T ----------------
#pragma unroll
    for (int q = 0; q < 4; q++)
#pragma unroll
        for (int p = 0; p < 4; p++) acc[q][p] = 0ull;

#pragma unroll
    for (int k4 = 0; k4 < NC; k4 += 4) {
        float4 av[4];
#pragma unroll
        for (int q = 0; q < 4; q++)
            av[q] = *(const float4*)&tile[(rg + 32 * q) * OTP + k4];
#pragma unroll
        for (int kk = 0; kk < 4; kk++) {
            const ulonglong2 bA = *(const ulonglong2*)&sWgT[(k4 + kk) * WTP + n0];
            const ulonglong2 bB = *(const ulonglong2*)&sWgT[(k4 + kk) * WTP + n0 + 4];
#pragma unroll
            for (int q = 0; q < 4; q++) {
                const float xs = (kk == 0) ? av[q].x : (kk == 1) ? av[q].y
                               : (kk == 2) ? av[q].z : av[q].w;
                const unsigned long long ap = pk2(xs, xs);
                acc[q][0] = f2fma(ap, bA.x, acc[q][0]);
                acc[q][1] = f2fma(ap, bA.y, acc[q][1]);
                acc[q][2] = f2fma(ap, bB.x, acc[q][2]);
                acc[q][3] = f2fma(ap, bB.y, acc[q][3]);
            }
        }
    }
    __syncthreads();   // everyone done reading X

    // sigmoid gate * ctx -> O tile (in place over X)
#pragma unroll
    for (int q = 0; q < 4; q++) {
        float ov[8];
#pragma unroll
        for (int p = 0; p < 4; p++) upk2(acc[q][p], ov[2 * p], ov[2 * p + 1]);
#pragma unroll
        for (int j = 0; j < 8; j++) {
            const float gv = ov[j] + sbg[n0 + j];
            ov[j] = sctx[n0 + j] * __fdividef(1.f, 1.f + __expf(-gv));
        }
        float* dst = &tile[(rg + 32 * q) * OTP + n0];
        *(float4*)dst       = make_float4(ov[0], ov[1], ov[2], ov[3]);
        *(float4*)(dst + 4) = make_float4(ov[4], ov[5], ov[6], ov[7]);
    }
    __syncthreads();

    // ---------------- GEMM2: out = O @ Wo^T + bo ----------------
#pragma unroll
    for (int q = 0; q < 4; q++)
#pragma unroll
        for (int p = 0; p < 4; p++) acc[q][p] = 0ull;

#pragma unroll
    for (int k4 = 0; k4 < NC; k4 += 4) {
        float4 av[4];
#pragma unroll
        for (int q = 0; q < 4; q++)
            av[q] = *(const float4*)&tile[(rg + 32 * q) * OTP + k4];
#pragma unroll
        for (int kk = 0; kk < 4; kk++) {
            const ulonglong2 bA = *(const ulonglong2*)&sWoT[(k4 + kk) * WTP + n0];
            const ulonglong2 bB = *(const ulonglong2*)&sWoT[(k4 + kk) * WTP + n0 + 4];
#pragma unroll
            for (int q = 0; q < 4; q++) {
                const float xs = (kk == 0) ? av[q].x : (kk == 1) ? av[q].y
                               : (kk == 2) ? av[q].z : av[q].w;
                const unsigned long long ap = pk2(xs, xs);
                acc[q][0] = f2fma(ap, bA.x, acc[q][0]);
                acc[q][1] = f2fma(ap, bA.y, acc[q][1]);
                acc[q][2] = f2fma(ap, bB.x, acc[q][2]);
                acc[q][3] = f2fma(ap, bB.y, acc[q][3]);
            }
        }
    }

    // epilogue: + bo, store direct to gmem (coalesced float4)
#pragma unroll
    for (int q = 0; q < 4; q++) {
        float ov[8];
#pragma unroll
        for (int p = 0; p < 4; p++) upk2(acc[q][p], ov[2 * p], ov[2 * p + 1]);
#pragma unroll
        for (int j = 0; j < 8; j++) ov[j] += sbo[n0 + j];
        const int r = rg + 32 * q;
        float* dst = &out[((size_t)(s0 + r) * NI + i) * NC + n0];
        *(float4*)dst       = make_float4(ov[0], ov[1], ov[2], ov[3]);
        *(float4*)(dst + 4) = make_float4(ov[4], ov[5], ov[6], ov[7]);
    }
}

// ==========================================================================
extern "C" void kernel_launch(void* const* d_in, const int* in_sizes, int n_in,
                              void* d_out, int out_size) {
    const float* m     = (const float*)d_in[0];
    const float* mask  = (const float*)d_in[1];
    const float* gamma = (const float*)d_in[2];
    const float* beta  = (const float*)d_in[3];
    const float* Wq    = (const float*)d_in[4];
    const float* Wk    = (const float*)d_in[5];
    const float* Wv    = (const float*)d_in[6];
    const float* Wg    = (const float*)d_in[7];
    const float* bg    = (const float*)d_in[8];
    const float* Wo    = (const float*)d_in[9];
    const float* bo    = (const float*)d_in[10];
    float* out = (float*)d_out;

    const int dsm_bytes = (TS * OTP + 2 * NC * WTP + 5 * 64) * 4;  // ~70 KB
    cudaFuncSetAttribute(k_out, cudaFuncAttributeMaxDynamicSharedMemorySize,
                         dsm_bytes);

    dim3 g1(NT, NI);
    k_pass1<<<g1, TS>>>(m, mask, gamma, beta, Wk, Wv);
    k_q<<<NI, 64>>>(mask, Wq);
    k_attn<<<NI, 256>>>(mask);
    dim3 g4(NT, NI);
    k_out<<<g4, 256, dsm_bytes>>>(m, gamma, beta, Wg, bg, Wo, bo, out);
}